// round 13
// baseline (speedup 1.0000x reference)
#include <cuda_runtime.h>
#include <cuda_bf16.h>
#include <stdint.h>

// ---------------- problem constants ----------------
#define NBATCH 128
#define SEQ    2048
#define DIM    256          // K (features)
#define ADIM   128          // N (attention dim)
#define TILES  2048         // M-tiles of 128 rows
#define GRID   152
#define NTHR   256

// smem layout (bytes)
#define SM_WF     0                       // 131072: W fragments (k-permuted)
#define OFF_SSC   131072                  // float[2][128] score partials (per colg)
#define OFF_SE    (131072 + 1024)         // float[2][128] exp(score), double buffered
#define OFF_SBIAS (131072 + 2048)         // float[128]
#define OFF_SCV   (131072 + 2560)         // float[128]
#define SM_TOTAL  (131072 + 3072)

// ---------------- device scratch ----------------
__device__ float g_partial[TILES * DIM];          // 2 MB
__device__ float g_esum[TILES];
__device__ unsigned g_count;                      // monotonic ticket barrier

// ---------------- helpers ----------------
__device__ __forceinline__ uint32_t pkbf(float a, float b) {
    __nv_bfloat162 t = __floats2bfloat162_rn(a, b);
    return *(uint32_t*)&t;
}
__device__ __forceinline__ void split2(float a, float b, uint32_t& hi, uint32_t& lo) {
    float ra = __bfloat162float(__float2bfloat16(a));
    float rb = __bfloat162float(__float2bfloat16(b));
    hi = pkbf(a, b);
    lo = pkbf(a - ra, b - rb);
}
__device__ __forceinline__ void mma_bf16(float c[4], uint32_t a0, uint32_t a1,
                                         uint32_t a2, uint32_t a3,
                                         uint32_t b0, uint32_t b1) {
    asm volatile(
        "mma.sync.aligned.m16n8k16.row.col.f32.bf16.bf16.f32 "
        "{%0,%1,%2,%3}, {%4,%5,%6,%7}, {%8,%9}, {%0,%1,%2,%3};"
        : "+f"(c[0]), "+f"(c[1]), "+f"(c[2]), "+f"(c[3])
        : "r"(a0), "r"(a1), "r"(a2), "r"(a3), "r"(b0), "r"(b1));
}
__device__ __forceinline__ float fast_tanh(float v) {
    float e = __expf(2.0f * v);
    return 1.0f - __fdividef(2.0f, e + 1.0f);
}

// ---------------- fused persistent kernel ----------------
__global__ void __launch_bounds__(NTHR, 1)
attn_fused(const float* __restrict__ x,
           const float* __restrict__ w,
           const float* __restrict__ bias,
           const float* __restrict__ cvec,
           float* __restrict__ out)
{
    extern __shared__ char smem[];
    uint4* sWf   = (uint4*)(smem + SM_WF);
    float* sSc   = (float*)(smem + OFF_SSC);         // [2][128]
    float* sE0   = (float*)(smem + OFF_SE);          // [2][128]
    float* sBias = (float*)(smem + OFF_SBIAS);
    float* sCv   = (float*)(smem + OFF_SCV);

    const int tid   = threadIdx.x;
    const int wid   = tid >> 5;
    const int lane  = tid & 31;
    const int g     = lane >> 2;      // 0..7
    const int tig   = lane & 3;       // 0..3
    const int rowg  = wid & 3;        // warp rows: rowg*32 .. +32
    const int colg  = wid >> 2;       // warp cols: colg*64 .. +64

    // ---- build W fragments (k-PERMUTED within each 16-chunk) ----
    // lane holds b0 = {w[k0],w[k0+1]}, b1 = {w[k0+2],w[k0+3]}, k0 = j*16 + 4*tig
    for (int idx = tid; idx < 16 * 16 * 32; idx += NTHR) {
        int ln = idx & 31, nf = (idx >> 5) & 15, j = idx >> 9;
        int gg = ln >> 2, tg = ln & 3;
        int n = nf * 8 + gg;
        int k0 = j * 16 + tg * 4;
        float w0 = w[(k0 + 0) * ADIM + n], w1 = w[(k0 + 1) * ADIM + n];
        float w2 = w[(k0 + 2) * ADIM + n], w3 = w[(k0 + 3) * ADIM + n];
        uint4 v;
        split2(w0, w1, v.x, v.z);
        split2(w2, w3, v.y, v.w);
        sWf[idx] = v;
    }
    if (tid < 128) { sBias[tid] = bias[tid]; sCv[tid] = cvec[tid]; }
    __syncthreads();

    int lastT = -1, lastbuf = 0, it = 0;

    for (int T = blockIdx.x; T < TILES; T += GRID, it++) {
        const int buf = it & 1;
        const size_t row0 = (size_t)T * 128;

        // this thread's 4 A-rows (2 mfrags x 2 rows): r, r+8, r+16, r+24
        const float* p0 = x + (row0 + rowg * 32 + g) * DIM + 4 * tig;
        const float* p1 = p0 + (size_t)8  * DIM;
        const float* p2 = p0 + (size_t)16 * DIM;
        const float* p3 = p0 + (size_t)24 * DIM;

        // interleaved weighted sum of previous tile (thread owns feature tid)
        const int Tprev = T - GRID;
        const bool havePrev = (it > 0);
        const float* xprev = x + (size_t)(havePrev ? Tprev : T) * 128 * DIM + tid;
        const float* sEp = sE0 + (buf ^ 1) * 128;
        float wacc = 0.0f;

        float acc[2][8][4];
        #pragma unroll
        for (int mf = 0; mf < 2; mf++)
            #pragma unroll
            for (int nf = 0; nf < 8; nf++)
                #pragma unroll
                for (int c = 0; c < 4; c++) acc[mf][nf][c] = 0.0f;

        float4 n0 = *(const float4*)p0;
        float4 n1 = *(const float4*)p1;
        float4 n2 = *(const float4*)p2;
        float4 n3 = *(const float4*)p3;

        #pragma unroll 1
        for (int j = 0; j < 16; j++) {
            // prev-tile weighted-sum loads (hide under MMAs)
            float wv[8];
            if (havePrev) {
                #pragma unroll
                for (int q = 0; q < 8; q++)
                    wv[q] = __ldg(xprev + (size_t)(j * 8 + q) * DIM);
            }

            float4 c0 = n0, c1 = n1, c2 = n2, c3 = n3;
            if (j < 15) {
                int o = (j + 1) * 16;
                n0 = *(const float4*)(p0 + o);
                n1 = *(const float4*)(p1 + o);
                n2 = *(const float4*)(p2 + o);
                n3 = *(const float4*)(p3 + o);
            }

            // fragments: a0={r,kp0} a1={r+8,kp0} a2={r,kp1} a3={r+8,kp1}
            uint32_t a0h, a1h, a2h, a3h, a0l, a1l, a2l, a3l;   // mfrag0
            uint32_t b0h, b1h, b2h, b3h, b0l, b1l, b2l, b3l;   // mfrag1
            split2(c0.x, c0.y, a0h, a0l);  split2(c0.z, c0.w, a2h, a2l);
            split2(c1.x, c1.y, a1h, a1l);  split2(c1.z, c1.w, a3h, a3l);
            split2(c2.x, c2.y, b0h, b0l);  split2(c2.z, c2.w, b2h, b2l);
            split2(c3.x, c3.y, b1h, b1l);  split2(c3.z, c3.w, b3h, b3l);

            const uint4* bp = sWf + (j * 16 + colg * 8) * 32 + lane;
            #pragma unroll
            for (int nf = 0; nf < 8; nf++) {
                uint4 B = bp[nf * 32];
                mma_bf16(acc[0][nf], a0h, a1h, a2h, a3h, B.x, B.y);   // hi*hi
                mma_bf16(acc[0][nf], a0h, a1h, a2h, a3h, B.z, B.w);   // hi*lo
                mma_bf16(acc[0][nf], a0l, a1l, a2l, a3l, B.x, B.y);   // lo*hi
                mma_bf16(acc[1][nf], b0h, b1h, b2h, b3h, B.x, B.y);
                mma_bf16(acc[1][nf], b0h, b1h, b2h, b3h, B.z, B.w);
                mma_bf16(acc[1][nf], b0l, b1l, b2l, b3l, B.x, B.y);
            }

            if (havePrev) {
                #pragma unroll
                for (int q = 0; q < 8; q++)
                    wacc = fmaf(sEp[j * 8 + q], wv[q], wacc);
            }
        }

        if (havePrev)
            g_partial[(size_t)Tprev * DIM + tid] = wacc;

        // ---- score partials: this warp's 64 cols, 32 rows ----
        #pragma unroll
        for (int mf = 0; mf < 2; mf++) {
            float s1 = 0.0f, s2 = 0.0f;
            #pragma unroll
            for (int nf = 0; nf < 8; nf++) {
                int col = colg * 64 + nf * 8 + 2 * tig;
                s1 += sCv[col]     * fast_tanh(acc[mf][nf][0] + sBias[col]);
                s1 += sCv[col + 1] * fast_tanh(acc[mf][nf][1] + sBias[col + 1]);
                s2 += sCv[col]     * fast_tanh(acc[mf][nf][2] + sBias[col]);
                s2 += sCv[col + 1] * fast_tanh(acc[mf][nf][3] + sBias[col + 1]);
            }
            s1 += __shfl_xor_sync(0xFFFFFFFFu, s1, 1);
            s1 += __shfl_xor_sync(0xFFFFFFFFu, s1, 2);
            s2 += __shfl_xor_sync(0xFFFFFFFFu, s2, 1);
            s2 += __shfl_xor_sync(0xFFFFFFFFu, s2, 2);
            if (tig == 0) {
                int r = rowg * 32 + mf * 16 + g;
                sSc[colg * 128 + r]     = s1;
                sSc[colg * 128 + r + 8] = s2;
            }
        }
        __syncthreads();   // sync #1: score partials visible

        if (tid < 128)
            sE0[buf * 128 + tid] = __expf(sSc[tid] + sSc[128 + tid]);
        __syncthreads();   // sync #2: sE[buf] visible

        if (tid < 32) {
            const float* sEc = sE0 + buf * 128;
            float e = sEc[tid] + sEc[tid + 32] + sEc[tid + 64] + sEc[tid + 96];
            e += __shfl_xor_sync(0xFFFFFFFFu, e, 16);
            e += __shfl_xor_sync(0xFFFFFFFFu, e, 8);
            e += __shfl_xor_sync(0xFFFFFFFFu, e, 4);
            e += __shfl_xor_sync(0xFFFFFFFFu, e, 2);
            e += __shfl_xor_sync(0xFFFFFFFFu, e, 1);
            if (tid == 0) g_esum[T] = e;
        }

        lastT = T; lastbuf = buf;
    }

    // ---- drain: weighted sum for the final tile ----
    if (lastT >= 0) {
        const float* sEc = sE0 + lastbuf * 128;
        const float* xp = x + (size_t)lastT * 128 * DIM + tid;
        float wacc = 0.0f;
        #pragma unroll 16
        for (int t = 0; t < 128; t++)
            wacc = fmaf(sEc[t], __ldg(xp + (size_t)t * DIM), wacc);
        g_partial[(size_t)lastT * DIM + tid] = wacc;
    }

    // ---- grid-wide ticket barrier (monotonic: graph-replay safe) ----
    __threadfence();
    __syncthreads();
    if (tid == 0) {
        unsigned t = atomicAdd(&g_count, 1u);
        unsigned target = (t / GRID + 1u) * GRID;
        while (atomicAdd(&g_count, 0u) < target) { __nanosleep(64); }
    }
    __syncthreads();

    // ---- finish: combine 16 splits per batch ----
    if (blockIdx.x < NBATCH && tid < DIM) {
        const int b = blockIdx.x;
        float s = 0.0f, es = 0.0f;
        #pragma unroll
        for (int sp = 0; sp < 16; sp++) {
            s  += __ldcg(&g_partial[(size_t)(b * 16 + sp) * DIM + tid]);
            es += __ldcg(&g_esum[b * 16 + sp]);
        }
        out[b * DIM + tid] = s / (es + 1e-10f);
    }
}

extern "C" void kernel_launch(void* const* d_in, const int* in_sizes, int n_in,
                              void* d_out, int out_size)
{
    const float* x    = (const float*)d_in[0];
    const float* w    = (const float*)d_in[1];
    const float* bias = (const float*)d_in[2];
    const float* cvec = (const float*)d_in[3];
    float* out = (float*)d_out;

    cudaFuncSetAttribute(attn_fused, cudaFuncAttributeMaxDynamicSharedMemorySize, SM_TOTAL);
    attn_fused<<<GRID, NTHR, SM_TOTAL>>>(x, w, bias, cvec, out);
}

// round 14
// speedup vs baseline: 1.1791x; 1.1791x over previous
#include <cuda_runtime.h>
#include <cuda_bf16.h>
#include <stdint.h>

// ---------------- problem constants ----------------
#define NBATCH 128
#define SEQ    2048
#define DIM    256          // K (features)
#define ADIM   128          // N (attention dim)
#define TILES  2048         // M-tiles of 128 rows
#define GRID   152
#define NTHR   512

// smem layout (bytes)
#define SM_WF     0                       // 131072: W fragments (k-permuted)
#define OFF_SSC   131072                  // float[2][128] score partials (per colg)
#define OFF_SE    (131072 + 1024)         // float[2][128] exp(score), double buffered
#define OFF_SRED  (131072 + 2048)         // float[256] ws half combine
#define OFF_SBIAS (131072 + 3072)         // float[128]
#define OFF_SCV   (131072 + 3584)         // float[128]
#define SM_TOTAL  (131072 + 4096)

// ---------------- device scratch ----------------
__device__ float g_partial[TILES * DIM];          // 2 MB
__device__ float g_esum[TILES];
__device__ unsigned g_count;                      // monotonic ticket barrier

// ---------------- helpers ----------------
__device__ __forceinline__ uint32_t pkbf(float a, float b) {
    __nv_bfloat162 t = __floats2bfloat162_rn(a, b);
    return *(uint32_t*)&t;
}
__device__ __forceinline__ void split2(float a, float b, uint32_t& hi, uint32_t& lo) {
    float ra = __bfloat162float(__float2bfloat16(a));
    float rb = __bfloat162float(__float2bfloat16(b));
    hi = pkbf(a, b);
    lo = pkbf(a - ra, b - rb);
}
__device__ __forceinline__ void mma_bf16(float c[4], uint32_t a0, uint32_t a1,
                                         uint32_t a2, uint32_t a3,
                                         uint32_t b0, uint32_t b1) {
    asm volatile(
        "mma.sync.aligned.m16n8k16.row.col.f32.bf16.bf16.f32 "
        "{%0,%1,%2,%3}, {%4,%5,%6,%7}, {%8,%9}, {%0,%1,%2,%3};"
        : "+f"(c[0]), "+f"(c[1]), "+f"(c[2]), "+f"(c[3])
        : "r"(a0), "r"(a1), "r"(a2), "r"(a3), "r"(b0), "r"(b1));
}
__device__ __forceinline__ float fast_tanh(float v) {
    float e = __expf(2.0f * v);
    return 1.0f - __fdividef(2.0f, e + 1.0f);
}

// ---------------- fused persistent kernel ----------------
__global__ void __launch_bounds__(NTHR, 1)
attn_fused(const float* __restrict__ x,
           const float* __restrict__ w,
           const float* __restrict__ bias,
           const float* __restrict__ cvec,
           float* __restrict__ out)
{
    extern __shared__ char smem[];
    uint4* sWf   = (uint4*)(smem + SM_WF);
    float* sSc   = (float*)(smem + OFF_SSC);         // [2][128]
    float* sE0   = (float*)(smem + OFF_SE);          // [2][128]
    float* sRed  = (float*)(smem + OFF_SRED);        // [256]
    float* sBias = (float*)(smem + OFF_SBIAS);
    float* sCv   = (float*)(smem + OFF_SCV);

    const int tid   = threadIdx.x;
    const int wid   = tid >> 5;
    const int lane  = tid & 31;
    const int g     = lane >> 2;      // 0..7
    const int tig   = lane & 3;       // 0..3
    const int rowg  = wid & 7;        // warp rows: rowg*16 .. +16
    const int colg  = wid >> 3;       // warp cols: colg*64 .. +64

    const int d_ws = tid & 255;       // weighted-sum feature
    const int h_ws = tid >> 8;        // weighted-sum t-half

    // ---- build W fragments (k-PERMUTED within each 16-chunk) ----
    // lane: b0 = {w[k0],w[k0+1]}, b1 = {w[k0+2],w[k0+3]}, k0 = j*16 + 4*tig
    for (int idx = tid; idx < 16 * 16 * 32; idx += NTHR) {
        int ln = idx & 31, nf = (idx >> 5) & 15, j = idx >> 9;
        int gg = ln >> 2, tg = ln & 3;
        int n = nf * 8 + gg;
        int k0 = j * 16 + tg * 4;
        float w0 = w[(k0 + 0) * ADIM + n], w1 = w[(k0 + 1) * ADIM + n];
        float w2 = w[(k0 + 2) * ADIM + n], w3 = w[(k0 + 3) * ADIM + n];
        uint4 v;
        split2(w0, w1, v.x, v.z);
        split2(w2, w3, v.y, v.w);
        sWf[idx] = v;
    }
    if (tid < 128) { sBias[tid] = bias[tid]; sCv[tid] = cvec[tid]; }
    __syncthreads();

    int lastT = -1, lastbuf = 0, it = 0;

    for (int T = blockIdx.x; T < TILES; T += GRID, it++) {
        const int buf = it & 1;
        const size_t row0 = (size_t)T * 128;

        // this thread's 2 A-rows: r = rowg*16 + g, and r+8
        const float* p0 = x + (row0 + rowg * 16 + g) * DIM + 4 * tig;
        const float* p1 = p0 + (size_t)8 * DIM;

        // interleaved weighted sum of previous tile
        const int Tprev = T - GRID;
        const bool havePrev = (it > 0);
        const float* xprev = x + ((size_t)(havePrev ? Tprev : T) * 128 + h_ws * 64) * DIM + d_ws;
        const float* sEp = sE0 + (buf ^ 1) * 128 + h_ws * 64;
        float wacc = 0.0f;

        float acc[8][4];
        #pragma unroll
        for (int nf = 0; nf < 8; nf++)
            #pragma unroll
            for (int c = 0; c < 4; c++) acc[nf][c] = 0.0f;

        float4 n0 = *(const float4*)p0;
        float4 n1 = *(const float4*)p1;

        #pragma unroll 1
        for (int j = 0; j < 16; j++) {
            // prev-tile weighted-sum loads (hide under MMAs)
            float wv[4];
            if (havePrev) {
                #pragma unroll
                for (int q = 0; q < 4; q++)
                    wv[q] = __ldg(xprev + (size_t)(j * 4 + q) * DIM);
            }

            float4 c0 = n0, c1 = n1;
            if (j < 15) {
                int o = (j + 1) * 16;
                n0 = *(const float4*)(p0 + o);
                n1 = *(const float4*)(p1 + o);
            }

            // fragments: a0={r,kp0} a1={r+8,kp0} a2={r,kp1} a3={r+8,kp1}
            uint32_t a0h, a1h, a2h, a3h, a0l, a1l, a2l, a3l;
            split2(c0.x, c0.y, a0h, a0l);  split2(c0.z, c0.w, a2h, a2l);
            split2(c1.x, c1.y, a1h, a1l);  split2(c1.z, c1.w, a3h, a3l);

            const uint4* bp = sWf + (j * 16 + colg * 8) * 32 + lane;
            #pragma unroll
            for (int nf = 0; nf < 8; nf++) {
                uint4 B = bp[nf * 32];
                mma_bf16(acc[nf], a0h, a1h, a2h, a3h, B.x, B.y);   // hi*hi
                mma_bf16(acc[nf], a0h, a1h, a2h, a3h, B.z, B.w);   // hi*lo
                mma_bf16(acc[nf], a0l, a1l, a2l, a3l, B.x, B.y);   // lo*hi
            }

            if (havePrev) {
                #pragma unroll
                for (int q = 0; q < 4; q++)
                    wacc = fmaf(sEp[j * 4 + q], wv[q], wacc);
            }
        }

        if (havePrev && h_ws == 0) sRed[d_ws] = wacc;

        // ---- score partials: this warp's 64 cols, 16 rows ----
        {
            float s1 = 0.0f, s2 = 0.0f;
            #pragma unroll
            for (int nf = 0; nf < 8; nf++) {
                int col = colg * 64 + nf * 8 + 2 * tig;
                s1 += sCv[col]     * fast_tanh(acc[nf][0] + sBias[col]);
                s1 += sCv[col + 1] * fast_tanh(acc[nf][1] + sBias[col + 1]);
                s2 += sCv[col]     * fast_tanh(acc[nf][2] + sBias[col]);
                s2 += sCv[col + 1] * fast_tanh(acc[nf][3] + sBias[col + 1]);
            }
            s1 += __shfl_xor_sync(0xFFFFFFFFu, s1, 1);
            s1 += __shfl_xor_sync(0xFFFFFFFFu, s1, 2);
            s2 += __shfl_xor_sync(0xFFFFFFFFu, s2, 1);
            s2 += __shfl_xor_sync(0xFFFFFFFFu, s2, 2);
            if (tig == 0) {
                int r = rowg * 16 + g;
                sSc[colg * 128 + r]     = s1;
                sSc[colg * 128 + r + 8] = s2;
            }
        }
        __syncthreads();   // sync #1: sRed(h0) + score partials visible

        if (havePrev && h_ws == 1)
            g_partial[(size_t)Tprev * DIM + d_ws] = sRed[d_ws] + wacc;

        if (tid < 128)
            sE0[buf * 128 + tid] = __expf(sSc[tid] + sSc[128 + tid]);
        __syncthreads();   // sync #2: sE[buf] visible

        if (tid < 32) {
            const float* sEc = sE0 + buf * 128;
            float e = sEc[tid] + sEc[tid + 32] + sEc[tid + 64] + sEc[tid + 96];
            e += __shfl_xor_sync(0xFFFFFFFFu, e, 16);
            e += __shfl_xor_sync(0xFFFFFFFFu, e, 8);
            e += __shfl_xor_sync(0xFFFFFFFFu, e, 4);
            e += __shfl_xor_sync(0xFFFFFFFFu, e, 2);
            e += __shfl_xor_sync(0xFFFFFFFFu, e, 1);
            if (tid == 0) g_esum[T] = e;
        }

        lastT = T; lastbuf = buf;
    }

    // ---- drain: weighted sum for the final tile ----
    if (lastT >= 0) {
        const float* sEc = sE0 + lastbuf * 128 + h_ws * 64;
        const float* xp = x + ((size_t)lastT * 128 + h_ws * 64) * DIM + d_ws;
        float wacc = 0.0f;
        #pragma unroll 16
        for (int t = 0; t < 64; t++)
            wacc = fmaf(sEc[t], __ldg(xp + (size_t)t * DIM), wacc);
        if (h_ws == 0) sRed[d_ws] = wacc;
        __syncthreads();
        if (h_ws == 1)
            g_partial[(size_t)lastT * DIM + d_ws] = sRed[d_ws] + wacc;
    }

    // ---- grid-wide ticket barrier (monotonic: graph-replay safe) ----
    __threadfence();
    __syncthreads();
    if (tid == 0) {
        unsigned t = atomicAdd(&g_count, 1u);
        unsigned target = (t / GRID + 1u) * GRID;
        while (atomicAdd(&g_count, 0u) < target) { __nanosleep(64); }
    }
    __syncthreads();

    // ---- finish: combine 16 splits per batch ----
    if (blockIdx.x < NBATCH && tid < DIM) {
        const int b = blockIdx.x;
        float s = 0.0f, es = 0.0f;
        #pragma unroll
        for (int sp = 0; sp < 16; sp++) {
            s  += __ldcg(&g_partial[(size_t)(b * 16 + sp) * DIM + tid]);
            es += __ldcg(&g_esum[b * 16 + sp]);
        }
        out[b * DIM + tid] = s / (es + 1e-10f);
    }
}

extern "C" void kernel_launch(void* const* d_in, const int* in_sizes, int n_in,
                              void* d_out, int out_size)
{
    const float* x    = (const float*)d_in[0];
    const float* w    = (const float*)d_in[1];
    const float* bias = (const float*)d_in[2];
    const float* cvec = (const float*)d_in[3];
    float* out = (float*)d_out;

    cudaFuncSetAttribute(attn_fused, cudaFuncAttributeMaxDynamicSharedMemorySize, SM_TOTAL);
    attn_fused<<<GRID, NTHR, SM_TOTAL>>>(x, w, bias, cvec, out);
}